// round 6
// baseline (speedup 1.0000x reference)
#include <cuda_runtime.h>
#include <stdint.h>
#include <math.h>

// Problem constants (fixed by the dataset problem)
#define KST   4096   // number of states
#define NSEQ  8192   // number of sequences
#define SLEN  1024   // sequence length

// Scratch (allocation-free rule: __device__ globals)
__device__ float g_log_init[KST];
__device__ float g_log_trans[(size_t)KST * KST];   // 64 MB, L2-resident
__device__ uint2 g_step_keys[SLEN];

// ---------------------------------------------------------------------------
// Threefry-2x32 (20 rounds), bit-exact vs jax/_src/prng.py / Random123
// ---------------------------------------------------------------------------
__host__ __device__ __forceinline__ uint32_t rotl32(uint32_t x, int r) {
#ifdef __CUDA_ARCH__
    return __funnelshift_l(x, x, r);
#else
    return (x << r) | (x >> (32 - r));
#endif
}

__host__ __device__ __forceinline__ void threefry2x32(
    uint32_t k0, uint32_t k1, uint32_t x0, uint32_t x1,
    uint32_t* o0, uint32_t* o1)
{
    const uint32_t k2 = k0 ^ k1 ^ 0x1BD11BDAu;
    x0 += k0; x1 += k1;
#define TF_R(r) { x0 += x1; x1 = rotl32(x1, (r)); x1 ^= x0; }
    TF_R(13) TF_R(15) TF_R(26) TF_R(6)
    x0 += k1; x1 += k2 + 1u;
    TF_R(17) TF_R(29) TF_R(16) TF_R(24)
    x0 += k2; x1 += k0 + 2u;
    TF_R(13) TF_R(15) TF_R(26) TF_R(6)
    x0 += k0; x1 += k1 + 3u;
    TF_R(17) TF_R(29) TF_R(16) TF_R(24)
    x0 += k1; x1 += k2 + 4u;
    TF_R(13) TF_R(15) TF_R(26) TF_R(6)
    x0 += k2; x1 += k0 + 5u;
#undef TF_R
    *o0 = x0; *o1 = x1;
}

// ---------------------------------------------------------------------------
// Prep: log(init), log(trans) (libdevice logf == XLA-GPU log lowering),
// and the 1024 per-step keys.
//   step 0 key = k0 (partitionable split child 0, computed on host)
//   step s key = fold_in(kloop, s) = full pair of tf(kloop, (0, s))
// ---------------------------------------------------------------------------
__global__ void prep_kernel(const float* __restrict__ init_p,
                            const float* __restrict__ trans_p,
                            uint32_t key0x, uint32_t key0y,
                            uint32_t kloopx, uint32_t kloopy)
{
    const long long idx    = (long long)blockIdx.x * blockDim.x + threadIdx.x;
    const long long stride = (long long)gridDim.x * blockDim.x;
    const long long total  = (long long)KST * KST;
    for (long long i = idx; i < total; i += stride)
        g_log_trans[i] = logf(trans_p[i]);
    if (idx < KST)
        g_log_init[idx] = logf(init_p[idx]);
    if (idx < SLEN) {
        if (idx == 0) {
            g_step_keys[0] = make_uint2(key0x, key0y);
        } else {
            uint32_t o0, o1;
            threefry2x32(kloopx, kloopy, 0u, (uint32_t)idx, &o0, &o1);
            g_step_keys[idx] = make_uint2(o0, o1);
        }
    }
}

// ---------------------------------------------------------------------------
// Main: PARTITIONABLE threefry random_bits layout (JAX >= 0.4.36 default):
//   bits[e] = o0 ^ o1 of tf(key, (hi=0, lo=e)),  e = n*K + k  (< 2^25, hi=0)
// One persistent block per sequence; 1024 autoregressive steps; per-step
// block-wide gumbel-argmax over K=4096 with first-index tie-breaking
// (== XLA argmax). OUTPUT IS WRITTEN AS FLOAT32 (harness output dtype).
// ---------------------------------------------------------------------------
__global__ void __launch_bounds__(256)
sample_kernel(float* __restrict__ out)
{
    const int n    = blockIdx.x;
    const int tid  = threadIdx.x;
    const int lane = tid & 31;
    const int warp = tid >> 5;

    __shared__ float s_val[8];
    __shared__ int   s_idx[8];
    __shared__ int   s_prev;

    const uint32_t ebase   = (uint32_t)n * (uint32_t)KST;
    const float    TINY32  = 1.17549435e-38f;   // finfo(f32).tiny
    const float    NEG_INF = __int_as_float(0xff800000);

    int prev = 0;  // unused at s=0 (uses log_init)

    for (int s = 0; s < SLEN; ++s) {
        const uint2 key = g_step_keys[s];
        const float* __restrict__ row =
            (s == 0) ? g_log_init : (g_log_trans + (size_t)prev * KST);

        float best = NEG_INF;
        int   bidx = 0;

#pragma unroll 4
        for (int j = 0; j < KST / 256; ++j) {
            const int k = tid + j * 256;
            uint32_t o0, o1;
            threefry2x32(key.x, key.y, 0u, ebase + (uint32_t)k, &o0, &o1);
            const uint32_t bits = o0 ^ o1;   // partitionable 32-bit path
            // uniform(minval=tiny, maxval=1):
            //   f = bitcast((bits>>9)|0x3f800000) - 1
            //   u = max(tiny, f*(1-tiny)+tiny) ; (1-tiny) == 1.0f exactly
            const float f = __uint_as_float((bits >> 9) | 0x3f800000u) - 1.0f;
            const float u = fmaxf(TINY32, f + TINY32);
            const float g = -logf(-logf(u));   // libdevice __nv_logf
            const float v = g + __ldg(row + k);
            if (v > best) { best = v; bidx = k; }   // strict > : first max per thread
        }

        // warp argmax-reduce; ties -> smaller global index (XLA first-max)
        for (int off = 16; off > 0; off >>= 1) {
            const float ov = __shfl_down_sync(0xffffffffu, best, off);
            const int   oi = __shfl_down_sync(0xffffffffu, bidx, off);
            if (ov > best || (ov == best && oi < bidx)) { best = ov; bidx = oi; }
        }
        if (lane == 0) { s_val[warp] = best; s_idx[warp] = bidx; }
        __syncthreads();

        if (warp == 0) {
            float v2 = (lane < 8) ? s_val[lane] : NEG_INF;
            int   i2 = (lane < 8) ? s_idx[lane] : 0x7fffffff;
            for (int off = 4; off > 0; off >>= 1) {
                const float ov = __shfl_down_sync(0xffffffffu, v2, off);
                const int   oi = __shfl_down_sync(0xffffffffu, i2, off);
                if (ov > v2 || (ov == v2 && oi < i2)) { v2 = ov; i2 = oi; }
            }
            if (lane == 0) {
                s_prev = i2;
                // OUTPUT DTYPE FIX: harness compares float32; int-bit writes
                // read as denormals ~0 and scored rel_err == 1.0 exactly.
                out[(size_t)n * SLEN + s] = (float)i2;
            }
        }
        __syncthreads();
        prev = s_prev;
    }
}

// ---------------------------------------------------------------------------
extern "C" void kernel_launch(void* const* d_in, const int* in_sizes, int n_in,
                              void* d_out, int out_size)
{
    const float* init_p  = (const float*)d_in[0];
    const float* trans_p = (const float*)d_in[1];
    float*       out     = (float*)d_out;

    // key = jax.random.key(42) -> threefry key (0, 42)
    // partitionable split: child i = full output pair of tf(master, (0, i))
    uint32_t a0, a1, b0, b1;
    threefry2x32(0u, 42u, 0u, 0u, &a0, &a1);   // k0    (first-state categorical)
    threefry2x32(0u, 42u, 0u, 1u, &b0, &b1);   // kloop (fold_in base)

    prep_kernel<<<4096, 256>>>(init_p, trans_p, a0, a1, b0, b1);
    sample_kernel<<<NSEQ, 256>>>(out);
}

// round 7
// speedup vs baseline: 1.1499x; 1.1499x over previous
#include <cuda_runtime.h>
#include <stdint.h>
#include <math.h>

// Problem constants (fixed by the dataset problem)
#define KST   4096   // number of states
#define NSEQ  8192   // number of sequences
#define SLEN  1024   // sequence length

// Scratch (allocation-free rule: __device__ globals)
__device__ float g_log_init[KST];
__device__ float g_log_trans[(size_t)KST * KST];   // 64 MB, L2-resident
__device__ uint2 g_step_keys[SLEN];
__device__ unsigned int g_rowmax_bits;             // float bits of max(log) (<0)

// ---------------------------------------------------------------------------
// Threefry-2x32 (20 rounds) — host/prep version
// ---------------------------------------------------------------------------
__host__ __device__ __forceinline__ uint32_t rotl32(uint32_t x, int r) {
#ifdef __CUDA_ARCH__
    return __funnelshift_l(x, x, r);
#else
    return (x << r) | (x >> (32 - r));
#endif
}

__host__ __device__ __forceinline__ void threefry2x32(
    uint32_t k0, uint32_t k1, uint32_t x0, uint32_t x1,
    uint32_t* o0, uint32_t* o1)
{
    const uint32_t k2 = k0 ^ k1 ^ 0x1BD11BDAu;
    x0 += k0; x1 += k1;
#define TF_R(r) { x0 += x1; x1 = rotl32(x1, (r)); x1 ^= x0; }
    TF_R(13) TF_R(15) TF_R(26) TF_R(6)
    x0 += k1; x1 += k2 + 1u;
    TF_R(17) TF_R(29) TF_R(16) TF_R(24)
    x0 += k2; x1 += k0 + 2u;
    TF_R(13) TF_R(15) TF_R(26) TF_R(6)
    x0 += k0; x1 += k1 + 3u;
    TF_R(17) TF_R(29) TF_R(16) TF_R(24)
    x0 += k1; x1 += k2 + 4u;
    TF_R(13) TF_R(15) TF_R(26) TF_R(6)
    x0 += k2; x1 += k0 + 5u;
#undef TF_R
    *o0 = x0; *o1 = x1;
}

// ---------------------------------------------------------------------------
// Reset (row-max accumulator must be deterministic per launch / graph replay)
// ---------------------------------------------------------------------------
__global__ void reset_kernel() { g_rowmax_bits = 0xFFFFFFFFu; }

// ---------------------------------------------------------------------------
// Prep: logs, step keys, and global row max (for the pruning threshold).
// All logs are < 0, so float-max == uint-bits-min -> atomicMin on bits.
// ---------------------------------------------------------------------------
__global__ void prep_kernel(const float* __restrict__ init_p,
                            const float* __restrict__ trans_p,
                            uint32_t key0x, uint32_t key0y,
                            uint32_t kloopx, uint32_t kloopy)
{
    __shared__ float sred[256];
    const long long idx    = (long long)blockIdx.x * blockDim.x + threadIdx.x;
    const long long stride = (long long)gridDim.x * blockDim.x;
    const long long total  = (long long)KST * KST;

    float lmax = -INFINITY;
    for (long long i = idx; i < total; i += stride) {
        const float l = logf(trans_p[i]);
        g_log_trans[i] = l;
        lmax = fmaxf(lmax, l);
    }
    if (idx < KST) {
        const float l = logf(init_p[idx]);
        g_log_init[idx] = l;
        lmax = fmaxf(lmax, l);
    }
    if (idx < SLEN) {
        if (idx == 0) {
            g_step_keys[0] = make_uint2(key0x, key0y);
        } else {
            uint32_t o0, o1;
            threefry2x32(kloopx, kloopy, 0u, (uint32_t)idx, &o0, &o1);
            g_step_keys[idx] = make_uint2(o0, o1);
        }
    }
    // block max -> one atomic per block
    sred[threadIdx.x] = lmax;
    __syncthreads();
    for (int o = 128; o > 0; o >>= 1) {
        if (threadIdx.x < o)
            sred[threadIdx.x] = fmaxf(sred[threadIdx.x], sred[threadIdx.x + o]);
        __syncthreads();
    }
    if (threadIdx.x == 0)
        atomicMin(&g_rowmax_bits, __float_as_uint(sred[0]));
}

// ---------------------------------------------------------------------------
// Main sampler.
//  - Threefry adds forced onto the FMA pipe (IMAD via runtime `one`);
//    SHF/LOP3 stay on ALU -> pipes balanced (was 85.9% ALU-bound).
//  - Exact-conservative pruning: gumbel is monotone in `bits`; a candidate
//    can only beat the warp's running best if bits >= bthr, where bthr is a
//    heavily under-padded inverse of u_thr = exp(-exp(-(best - R))),
//    R = global max log. Skipped elements are PROVABLY strictly below the
//    running best -> output bit-identical to the unpruned kernel.
// ---------------------------------------------------------------------------
__global__ void __launch_bounds__(256)
sample_kernel(float* __restrict__ out, uint32_t one)
{
    const int n    = blockIdx.x;
    const int tid  = threadIdx.x;
    const int lane = tid & 31;
    const int warp = tid >> 5;

    __shared__ unsigned s_m[8];
    __shared__ int      s_i[8];
    __shared__ int      s_prev;

    const uint32_t ebase  = (uint32_t)n * (uint32_t)KST;
    const float    TINY32 = 1.17549435e-38f;            // finfo(f32).tiny
    const float    R      = __uint_as_float(g_rowmax_bits);
    const unsigned MAP_NEG_INF = 0x007FFFFFu;           // mapped(-inf)

    int prev = 0;  // unused at s=0 (uses log_init)

    for (int s = 0; s < SLEN; ++s) {
        const uint2 key = g_step_keys[s];
        const float* __restrict__ row =
            (s == 0) ? g_log_init : (g_log_trans + (size_t)prev * KST);

        // hoisted key-injection constants
        const uint32_t k0 = key.x, k1 = key.y, kx = k0 ^ k1 ^ 0x1BD11BDAu;
        const uint32_t i1b = kx + 1u, i2b = k0 + 2u, i3b = k1 + 3u,
                       i4b = kx + 4u, i5b = k0 + 5u;
        const uint32_t x1base = k1 + ebase + (uint32_t)tid;

        unsigned best_m = MAP_NEG_INF;   // warp-shared (uniform) mapped best
        int      best_i = 0;
        uint32_t bthr   = 0u;            // candidate iff bits >= bthr; 0 = all

#pragma unroll 4
        for (int j = 0; j < KST / 256; ++j) {
            const int k = tid + j * 256;
            // threefry(key, (hi=0, lo=ebase+k)) ; x0 starts at k0 (hi==0)
            uint32_t x0 = k0;
            uint32_t x1 = one * (uint32_t)(j * 256) + x1base;
#define TFR(r) { x0 = one * x0 + x1; x1 = __funnelshift_l(x1, x1, (r)) ^ x0; }
            TFR(13) TFR(15) TFR(26) TFR(6)
            x0 = one * x0 + k1; x1 = one * x1 + i1b;
            TFR(17) TFR(29) TFR(16) TFR(24)
            x0 = one * x0 + kx; x1 = one * x1 + i2b;
            TFR(13) TFR(15) TFR(26) TFR(6)
            x0 = one * x0 + k0; x1 = one * x1 + i3b;
            TFR(17) TFR(29) TFR(16) TFR(24)
            x0 = one * x0 + k1; x1 = one * x1 + i4b;
            TFR(13) TFR(15) TFR(26) TFR(6)
            x0 = one * x0 + kx; x1 = one * x1 + i5b;
#undef TFR
            const uint32_t bits = x0 ^ x1;   // partitionable 32-bit path

            const bool pass = (bits >= bthr);
            if (__any_sync(0xffffffffu, pass)) {
                unsigned mk = MAP_NEG_INF;
                float v = 0.0f;
                if (pass) {
                    // uniform(tiny,1): f = bitcast((bits>>9)|0x3f800000)-1 ;
                    // u = max(tiny, f*(1-tiny)+tiny), (1-tiny)==1.0f exactly
                    const float f = __uint_as_float((bits >> 9) | 0x3f800000u) - 1.0f;
                    const float u = fmaxf(TINY32, f + TINY32);
                    const float g = -logf(-logf(u));     // libdevice logf (XLA-GPU)
                    v = g + __ldg(row + k);
                    const unsigned ub = __float_as_uint(v);
                    mk = (ub & 0x80000000u) ? ~ub : (ub | 0x80000000u); // order-map
                }
                const unsigned wm = __reduce_max_sync(0xffffffffu, mk);
                if (wm > best_m) {       // == keeps earlier (smaller) index
                    best_m = wm;
                    const unsigned sel = __ballot_sync(0xffffffffu, mk == wm);
                    const int src = __ffs(sel) - 1;      // lowest lane = lowest k
                    best_i = (warp << 5) + src + j * 256;
                    const float vb = __shfl_sync(0xffffffffu, v, src);
                    // conservative threshold: u_thr = exp(-exp(-(vb - R)))
                    const float t  = vb - R;
                    const float w  = expf(-t);
                    const float up = expf(-w) * 0.99998f;   // under-pad (>=10x err)
                    uint32_t nt = 0u;
                    if (up >= 1.0f) {
                        nt = 0xFFFFFFFFu;                   // nothing can win
                    } else if (up > 0.0f) {
                        const unsigned mant = __float_as_uint(1.0f + up) & 0x7FFFFFu;
                        nt = (mant > 8u) ? ((mant - 8u) << 9) : 0u;  // extra pad
                    }
                    bthr = nt;   // NaN-safe: falls through to 0 (compute all)
                }
            }
        }

        // combine the 8 warp results; ties -> smaller index (XLA first-max)
        if (lane == 0) { s_m[warp] = best_m; s_i[warp] = best_i; }
        __syncthreads();
        if (warp == 0) {
            unsigned m2 = (lane < 8) ? s_m[lane] : 0u;
            int      i2 = (lane < 8) ? s_i[lane] : 0x7FFFFFFF;
            for (int off = 4; off > 0; off >>= 1) {
                const unsigned om = __shfl_down_sync(0xffffffffu, m2, off);
                const int      oi = __shfl_down_sync(0xffffffffu, i2, off);
                if (om > m2 || (om == m2 && oi < i2)) { m2 = om; i2 = oi; }
            }
            if (lane == 0) {
                s_prev = i2;
                out[(size_t)n * SLEN + s] = (float)i2;   // harness dtype: f32
            }
        }
        __syncthreads();
        prev = s_prev;
    }
}

// ---------------------------------------------------------------------------
extern "C" void kernel_launch(void* const* d_in, const int* in_sizes, int n_in,
                              void* d_out, int out_size)
{
    const float* init_p  = (const float*)d_in[0];
    const float* trans_p = (const float*)d_in[1];
    float*       out     = (float*)d_out;

    // key = jax.random.key(42) -> threefry key (0, 42); partitionable split:
    // child i = full output pair of tf(master, (0, i))
    uint32_t a0, a1, b0, b1;
    threefry2x32(0u, 42u, 0u, 0u, &a0, &a1);   // k0    (first-state categorical)
    threefry2x32(0u, 42u, 0u, 1u, &b0, &b1);   // kloop (fold_in base)

    reset_kernel<<<1, 1>>>();
    prep_kernel<<<4096, 256>>>(init_p, trans_p, a0, a1, b0, b1);
    sample_kernel<<<NSEQ, 256>>>(out, 1u);
}

// round 8
// speedup vs baseline: 1.2469x; 1.0844x over previous
#include <cuda_runtime.h>
#include <stdint.h>
#include <math.h>

// Problem constants (fixed by the dataset problem)
#define KST   4096   // number of states
#define NSEQ  8192   // number of sequences
#define SLEN  1024   // sequence length

// Scratch (allocation-free rule: __device__ globals)
__device__ float g_log_init[KST];
__device__ float g_log_trans[(size_t)KST * KST];   // 64 MB, L2-resident
__device__ uint2 g_step_keys[SLEN];
__device__ unsigned int g_rowmax_bits;             // float bits of max(log) (<0)

// ---------------------------------------------------------------------------
// Threefry-2x32 (20 rounds) — host/prep version
// ---------------------------------------------------------------------------
__host__ __device__ __forceinline__ uint32_t rotl32(uint32_t x, int r) {
#ifdef __CUDA_ARCH__
    return __funnelshift_l(x, x, r);
#else
    return (x << r) | (x >> (32 - r));
#endif
}

__host__ __device__ __forceinline__ void threefry2x32(
    uint32_t k0, uint32_t k1, uint32_t x0, uint32_t x1,
    uint32_t* o0, uint32_t* o1)
{
    const uint32_t k2 = k0 ^ k1 ^ 0x1BD11BDAu;
    x0 += k0; x1 += k1;
#define TF_R(r) { x0 += x1; x1 = rotl32(x1, (r)); x1 ^= x0; }
    TF_R(13) TF_R(15) TF_R(26) TF_R(6)
    x0 += k1; x1 += k2 + 1u;
    TF_R(17) TF_R(29) TF_R(16) TF_R(24)
    x0 += k2; x1 += k0 + 2u;
    TF_R(13) TF_R(15) TF_R(26) TF_R(6)
    x0 += k0; x1 += k1 + 3u;
    TF_R(17) TF_R(29) TF_R(16) TF_R(24)
    x0 += k1; x1 += k2 + 4u;
    TF_R(13) TF_R(15) TF_R(26) TF_R(6)
    x0 += k2; x1 += k0 + 5u;
#undef TF_R
    *o0 = x0; *o1 = x1;
}

// ---------------------------------------------------------------------------
__global__ void reset_kernel() { g_rowmax_bits = 0xFFFFFFFFu; }

// ---------------------------------------------------------------------------
// Prep: logs, step keys, and global max-log (for the pruning threshold).
// All logs are < 0, so float-max == uint-bits-min -> atomicMin on bits.
// ---------------------------------------------------------------------------
__global__ void prep_kernel(const float* __restrict__ init_p,
                            const float* __restrict__ trans_p,
                            uint32_t key0x, uint32_t key0y,
                            uint32_t kloopx, uint32_t kloopy)
{
    __shared__ float sred[256];
    const long long idx    = (long long)blockIdx.x * blockDim.x + threadIdx.x;
    const long long stride = (long long)gridDim.x * blockDim.x;
    const long long total  = (long long)KST * KST;

    float lmax = -INFINITY;
    for (long long i = idx; i < total; i += stride) {
        const float l = logf(trans_p[i]);
        g_log_trans[i] = l;
        lmax = fmaxf(lmax, l);
    }
    if (idx < KST) {
        const float l = logf(init_p[idx]);
        g_log_init[idx] = l;
        lmax = fmaxf(lmax, l);
    }
    if (idx < SLEN) {
        if (idx == 0) {
            g_step_keys[0] = make_uint2(key0x, key0y);
        } else {
            uint32_t o0, o1;
            threefry2x32(kloopx, kloopy, 0u, (uint32_t)idx, &o0, &o1);
            g_step_keys[idx] = make_uint2(o0, o1);
        }
    }
    sred[threadIdx.x] = lmax;
    __syncthreads();
    for (int o = 128; o > 0; o >>= 1) {
        if (threadIdx.x < o)
            sred[threadIdx.x] = fmaxf(sred[threadIdx.x], sred[threadIdx.x + o]);
        __syncthreads();
    }
    if (threadIdx.x == 0)
        atomicMin(&g_rowmax_bits, __float_as_uint(sred[0]));
}

// ---------------------------------------------------------------------------
// Conservative bits-threshold from a mapped achieved best value.
// u_thr = exp(-exp(-(vb - R))), heavily under-padded so every skipped
// element is PROVABLY strictly below vb -> argmax unchanged bit-for-bit.
// ---------------------------------------------------------------------------
__device__ __forceinline__ uint32_t thr_from_mapped(unsigned m, float R)
{
    const unsigned ub = (m & 0x80000000u) ? (m & 0x7FFFFFFFu) : ~m;  // unmap
    const float vb = __uint_as_float(ub);
    const float t  = vb - R;
    const float w  = expf(-t);
    const float up = expf(-w) * 0.99998f;                  // >=10x composed err
    uint32_t nt = 0u;
    if (up >= 1.0f) {
        nt = 0xFFFFFFFFu;
    } else if (up > 0.0f) {
        const unsigned mant = __float_as_uint(1.0f + up) & 0x7FFFFFu;
        nt = (mant > 8u) ? ((mant - 8u) << 9) : 0u;        // extra ulp pad
    }
    return nt;   // NaN / nonpositive -> 0 (compute everything)
}

// ---------------------------------------------------------------------------
// Main sampler.
//  - Threefry adds on the FMA pipe (IMAD via runtime `one`); SHF/LOP3 on ALU.
//  - BLOCK-shared prune threshold + argmax in ONE shared 64-bit word:
//      pack = (mapped_value << 32) | (0x7FFFFFFF - index)
//    updated with atomicMax (value-major; ties -> smaller index; associative
//    => deterministic). Threshold refreshed from the live block best each
//    batch -> float path ~9% of elements (was ~27% with warp-local best).
//  - ONE __syncthreads per step; 3-buffer rotation makes the reset of the
//    (s-1)%3 buffer race-free (its readers are ordered before this barrier).
// Output written as float32 (harness output dtype).
// ---------------------------------------------------------------------------
__global__ void __launch_bounds__(256)
sample_kernel(float* __restrict__ out, uint32_t one)
{
    const int n    = blockIdx.x;
    const int tid  = threadIdx.x;

    __shared__ unsigned long long s_pack[3];
    if (tid == 0) { s_pack[0] = 0ull; s_pack[1] = 0ull; s_pack[2] = 0ull; }
    __syncthreads();

    const uint32_t ebase  = (uint32_t)n * (uint32_t)KST;
    const float    TINY32 = 1.17549435e-38f;            // finfo(f32).tiny
    const float    R      = __uint_as_float(g_rowmax_bits);

    int prev = 0;  // unused at s=0 (uses log_init)

    for (int s = 0; s < SLEN; ++s) {
        const uint2 key = g_step_keys[s];
        const float* __restrict__ row =
            (s == 0) ? g_log_init : (g_log_trans + (size_t)prev * KST);

        const int bsel = s - (s / 3) * 3;               // s % 3
        unsigned long long* pk = &s_pack[bsel];
        const uint32_t pk_sa = (uint32_t)__cvta_generic_to_shared(pk);

        // hoisted key-injection constants
        const uint32_t k0 = key.x, k1 = key.y, kx = k0 ^ k1 ^ 0x1BD11BDAu;
        const uint32_t i1b = kx + 1u, i2b = k0 + 2u, i3b = k1 + 3u,
                       i4b = kx + 4u, i5b = k0 + 5u;
        const uint32_t x1base = k1 + ebase + (uint32_t)tid;

        unsigned last_sb = 0u;   // cached block-best (mapped); 0 < any real
        uint32_t bthr    = 0u;   // candidate iff bits >= bthr

#pragma unroll 4
        for (int j = 0; j < KST / 256; ++j) {
            // threefry(key, (hi=0, lo=ebase + tid + j*256)); x0 starts at k0
            uint32_t x0 = k0;
            uint32_t x1 = one * (uint32_t)(j * 256) + x1base;
#define TFR(r) { x0 = one * x0 + x1; x1 = __funnelshift_l(x1, x1, (r)) ^ x0; }
            TFR(13) TFR(15) TFR(26) TFR(6)
            x0 = one * x0 + k1; x1 = one * x1 + i1b;
            TFR(17) TFR(29) TFR(16) TFR(24)
            x0 = one * x0 + kx; x1 = one * x1 + i2b;
            TFR(13) TFR(15) TFR(26) TFR(6)
            x0 = one * x0 + k0; x1 = one * x1 + i3b;
            TFR(17) TFR(29) TFR(16) TFR(24)
            x0 = one * x0 + k1; x1 = one * x1 + i4b;
            TFR(13) TFR(15) TFR(26) TFR(6)
            x0 = one * x0 + kx; x1 = one * x1 + i5b;
#undef TFR
            const uint32_t bits = x0 ^ x1;   // partitionable 32-bit path

            // refresh threshold from the live block-shared best
            {
                unsigned long long sp;
                asm volatile("ld.shared.b64 %0, [%1];" : "=l"(sp) : "r"(pk_sa));
                const unsigned sb = (unsigned)(sp >> 32);
                if (sb > last_sb) { last_sb = sb; bthr = thr_from_mapped(sb, R); }
            }

            const bool pass = (bits >= bthr);
            if (__any_sync(0xffffffffu, pass)) {
                unsigned mk = 0u;
                if (pass) {
                    // uniform(tiny,1): f = bitcast((bits>>9)|0x3f800000)-1 ;
                    // u = max(tiny, f*(1-tiny)+tiny), (1-tiny)==1.0f exactly
                    const float f = __uint_as_float((bits >> 9) | 0x3f800000u) - 1.0f;
                    const float u = fmaxf(TINY32, f + TINY32);
                    const float g = -logf(-logf(u));    // libdevice logf (XLA-GPU)
                    const float v = g + __ldg(row + (tid + j * 256));
                    const unsigned ub = __float_as_uint(v);
                    mk = (ub & 0x80000000u) ? ~ub : (ub | 0x80000000u);  // order-map
                }
                const unsigned wm = __reduce_max_sync(0xffffffffu, mk);
                if (wm >= last_sb) {
                    const unsigned sel = __ballot_sync(0xffffffffu, mk == wm);
                    const int src = __ffs(sel) - 1;     // lowest lane = lowest k
                    const int idx = (tid & ~31) + src + j * 256;
                    const unsigned long long cand =
                        ((unsigned long long)wm << 32) |
                        (unsigned)(0x7FFFFFFF - idx);
                    atomicMax(pk, cand);
                    last_sb = wm;
                    bthr = thr_from_mapped(wm, R);
                }
            }
        }

        __syncthreads();                     // all atomicMax done; pack final
        const unsigned long long fp = *pk;   // ordered-after-barrier plain read
        prev = 0x7FFFFFFF - (int)(unsigned)(fp & 0xFFFFFFFFull);
        if (tid == 0) {
            out[(size_t)n * SLEN + s] = (float)prev;    // harness dtype: f32
            s_pack[(s + 2) % 3] = 0ull;      // distance-2 reuse: race-free
        }
    }
}

// ---------------------------------------------------------------------------
extern "C" void kernel_launch(void* const* d_in, const int* in_sizes, int n_in,
                              void* d_out, int out_size)
{
    const float* init_p  = (const float*)d_in[0];
    const float* trans_p = (const float*)d_in[1];
    float*       out     = (float*)d_out;

    // key = jax.random.key(42) -> threefry key (0, 42); partitionable split:
    // child i = full output pair of tf(master, (0, i))
    uint32_t a0, a1, b0, b1;
    threefry2x32(0u, 42u, 0u, 0u, &a0, &a1);   // k0    (first-state categorical)
    threefry2x32(0u, 42u, 0u, 1u, &b0, &b1);   // kloop (fold_in base)

    reset_kernel<<<1, 1>>>();
    prep_kernel<<<4096, 256>>>(init_p, trans_p, a0, a1, b0, b1);
    sample_kernel<<<NSEQ, 256>>>(out, 1u);
}